// round 1
// baseline (speedup 1.0000x reference)
#include <cuda_runtime.h>
#include <math.h>

// Problem constants (fixed shapes)
#define NB      2
#define CIN     64
#define HAX     56
#define WAX     56
#define BATCH   112          // NB*WAX
#define OUTC    64
#define NHASH   4
#define CHUNK   25
#define KBLK    3            // 75/25
#define T75     75
#define PADLEN  19
#define EPS_N   5e-5f

// -------------------- scratch (device globals; no allocation) --------------------
__device__ float g_wmatch[BATCH*56*32];       // (b, t, 32)
__device__ float g_vmatch[BATCH*56*64];       // (b, t, 64)
__device__ int   g_codes  [BATCH*224];
__device__ int   g_indices[BATCH*224];
__device__ int   g_undo   [BATCH*224];
__device__ float g_ret1[BATCH*38400];         // (b, g,h2,k,i,e16) flat
__device__ float g_bsg [BATCH*8*4*75];        // (b, g, h2, t75)
__device__ float g_rdnm[BATCH*300];           // 1/max(||.||,eps) over 128 channels
__device__ float g_bsn [BATCH*224];           // normalized bs, sorted order
__device__ float g_outs[BATCH*224*64];        // attention output, sorted order

// -------------------- kernel 1: conv1x1 + BN + reshape-scatter --------------------
__global__ void k_convbn(const float* __restrict__ x, const float* __restrict__ cw,
                         const float* __restrict__ gamma, const float* __restrict__ beta)
{
    int b = blockIdx.x; int n = b / WAX, w = b % WAX;
    __shared__ float xs[CIN*HAX];    // (c, h)
    __shared__ float ws[96*CIN];     // (o, c)
    for (int i = threadIdx.x; i < CIN*HAX; i += blockDim.x) {
        int c = i / HAX, h = i % HAX;
        xs[i] = x[((n*CIN + c)*HAX + h)*WAX + w];
    }
    for (int i = threadIdx.x; i < 96*CIN; i += blockDim.x) ws[i] = cw[i];
    __syncthreads();
    const float inv = rsqrtf(1.0f + 1e-5f);
    for (int i = threadIdx.x; i < 96*HAX; i += blockDim.x) {
        int o = i / HAX, h = i % HAX;
        float acc = 0.f;
        #pragma unroll 8
        for (int c = 0; c < CIN; c++) acc += ws[o*CIN + c] * xs[c*HAX + h];
        float v = acc * inv * gamma[o] + beta[o];
        // raw reshape (96,56) -> (56,96):  flat = o*56+h ; t = flat/96, f = flat%96
        int t = i / 96, f = i % 96;
        if (f < 32) g_wmatch[(b*56 + t)*32 + f]        = v;
        else        g_vmatch[(b*56 + t)*64 + (f - 32)] = v;
    }
}

// -------------------- kernel 2: rotations -> hash codes --------------------
__global__ void k_codes(const float* __restrict__ rot)   // rot: (32,4,1)
{
    int idx = blockIdx.x*blockDim.x + threadIdx.x;
    if (idx >= BATCH*224) return;
    int b = idx / 224, r = idx % 224, hh = r / 56, t = r % 56;
    const float* wrow = &g_wmatch[(b*56 + t)*32];
    float acc = 0.f;
    #pragma unroll
    for (int f = 0; f < 32; f++) acc += wrow[f] * rot[f*4 + hh];
    g_codes[idx] = ((acc < 0.0f) ? 1 : 0) + 2*hh;
}

// -------------------- kernel 3: stable counting sort + inverse --------------------
__global__ void k_sort()
{
    int b = blockIdx.x*blockDim.x + threadIdx.x;
    if (b >= BATCH) return;
    const int* cd = &g_codes[b*224];
    int cnt[8] = {0,0,0,0,0,0,0,0};
    for (int p = 0; p < 224; p++) cnt[cd[p]]++;
    int off[8]; int s = 0;
    for (int c = 0; c < 8; c++) { off[c] = s; s += cnt[c]; }
    int* ind = &g_indices[b*224];
    for (int p = 0; p < 224; p++) ind[off[cd[p]]++] = p;
    int* ud = &g_undo[b*224];
    for (int pos = 0; pos < 224; pos++) ud[ind[pos]] = pos;
}

// -------------------- kernel 4: fused chunked attention --------------------
struct SmemAtt {
    float w_t [8][3][25][4];   // gathered w rows (scrambled view)
    float invn[8][3][25];      // 1/max(||w||,eps)
    float v_t [8][3][25][8];   // gathered v rows
    float we  [3][25][4];      // w embedding (padded)
    float ve  [3][25][8];      // v embedding (padded)
    float s   [8][25][75];     // ss -> score (in place), per-k
};

__global__ void k_attn(const float* __restrict__ relative)  // relative: (56,12)
{
    extern __shared__ char smraw[];
    SmemAtt* sm = reinterpret_cast<SmemAtt*>(smraw);
    const int b = blockIdx.x, h2 = blockIdx.y;
    const int tid = threadIdx.x;

    // ---- gather tiles ----
    for (int idx = tid; idx < 8*75; idx += blockDim.x) {
        int g = idx / 75, rem = idx % 75;        // rem = k*25 + i
        int k = rem / 25, i = rem % 25;
        int tc  = (g & 1)*300 + h2*75 + rem;     // flat (t,c) within source hash
        int hp  = g >> 1;
        int tp  = tc >> 3, c = tc & 7;
        int t56 = (tp < 56) ? tp : tp - PADLEN;
        int src = g_indices[b*224 + hp*56 + t56] % 56;
        float4 wv = *reinterpret_cast<const float4*>(&g_wmatch[(b*56 + src)*32 + 4*c]);
        sm->w_t[g][k][i][0] = wv.x; sm->w_t[g][k][i][1] = wv.y;
        sm->w_t[g][k][i][2] = wv.z; sm->w_t[g][k][i][3] = wv.w;
        float nn = wv.x*wv.x + wv.y*wv.y + wv.z*wv.z + wv.w*wv.w;
        sm->invn[g][k][i] = 1.0f / fmaxf(sqrtf(nn), EPS_N);
        const float4* vp = reinterpret_cast<const float4*>(&g_vmatch[(b*56 + src)*64 + 8*c]);
        float4 v0 = vp[0], v1 = vp[1];
        sm->v_t[g][k][i][0] = v0.x; sm->v_t[g][k][i][1] = v0.y;
        sm->v_t[g][k][i][2] = v0.z; sm->v_t[g][k][i][3] = v0.w;
        sm->v_t[g][k][i][4] = v1.x; sm->v_t[g][k][i][5] = v1.y;
        sm->v_t[g][k][i][6] = v1.z; sm->v_t[g][k][i][7] = v1.w;
    }
    for (int idx = tid; idx < 75; idx += blockDim.x) {
        int k = idx / 25, i = idx % 25;
        int t56 = (idx < 56) ? idx : idx - PADLEN;
        const float* rr = &relative[t56*12];
        #pragma unroll
        for (int e = 0; e < 4; e++) sm->we[k][i][e] = rr[e];
        #pragma unroll
        for (int e = 0; e < 8; e++) sm->ve[k][i][e] = rr[4 + e];
    }
    __syncthreads();

    for (int k = 0; k < KBLK; k++) {
        const int kp = (k + 2) % 3, kn = (k + 1) % 3;

        // ---- phase 1: scores (raw + emb), cross-group L2 norm ----
        for (int pos = tid; pos < 25*75; pos += blockDim.x) {
            int i = pos / 75, j = pos % 75;
            int kk, jj;
            if (j < 25)      { kk = k;  jj = j;      }
            else if (j < 50) { kk = kp; jj = j - 25; }
            else             { kk = kn; jj = j - 50; }
            float we0 = sm->we[kk][jj][0], we1 = sm->we[kk][jj][1];
            float we2 = sm->we[kk][jj][2], we3 = sm->we[kk][jj][3];
            float vals[8]; float ssq = 0.f;
            #pragma unroll
            for (int g = 0; g < 8; g++) {
                const float* a  = sm->w_t[g][k][i];
                const float* mr = sm->w_t[g][kk][jj];
                float inm = sm->invn[g][kk][jj];
                float raw = (a[0]*mr[0] + a[1]*mr[1] + a[2]*mr[2] + a[3]*mr[3]) * inm;
                float emb = 0.1f * (a[0]*we0 + a[1]*we1 + a[2]*we2 + a[3]*we3);
                vals[g] = raw + emb;
                ssq += raw*raw + emb*emb;
            }
            float rd = 1.0f / fmaxf(sqrtf(ssq), EPS_N);
            #pragma unroll
            for (int g = 0; g < 8; g++) sm->s[g][i][j] = vals[g] * rd;
        }
        __syncthreads();

        // ---- phase 2: logsumexp per (g,i) row; score in place ----
        {
            int warp = tid >> 5, lane = tid & 31, nw = blockDim.x >> 5;
            for (int row = warp; row < 200; row += nw) {
                int g = row / 25, i = row % 25;
                float* r = sm->s[g][i];
                float m = -1e30f;
                for (int j = lane; j < 75; j += 32) m = fmaxf(m, r[j]);
                #pragma unroll
                for (int o = 16; o; o >>= 1) m = fmaxf(m, __shfl_xor_sync(~0u, m, o));
                float sum = 0.f;
                for (int j = lane; j < 75; j += 32) { float e = expf(r[j] - m); r[j] = e; sum += e; }
                #pragma unroll
                for (int o = 16; o; o >>= 1) sum += __shfl_xor_sync(~0u, sum, o);
                float rs = 1.0f / sum;
                for (int j = lane; j < 75; j += 32) r[j] *= rs;
                if (lane == 0)
                    g_bsg[((b*8 + g)*4 + h2)*75 + k*25 + i] = m + logf(sum);
            }
        }
        __syncthreads();

        // ---- phase 3: score @ V (adjacent) and score @ v_emb ----
        for (int o = tid; o < 8*25*16; o += blockDim.x) {
            int g = o / 400, rem = o % 400, i = rem / 16, e = rem % 16;
            const float* srow = sm->s[g][i];
            float acc = 0.f;
            if (e < 8) {
                #pragma unroll
                for (int j = 0; j < 25; j++) acc += srow[j]      * sm->v_t[g][k ][j][e];
                #pragma unroll
                for (int j = 0; j < 25; j++) acc += srow[25 + j] * sm->v_t[g][kp][j][e];
                #pragma unroll
                for (int j = 0; j < 25; j++) acc += srow[50 + j] * sm->v_t[g][kn][j][e];
            } else {
                int e8 = e - 8;
                #pragma unroll
                for (int j = 0; j < 25; j++) acc += srow[j]      * sm->ve[k ][j][e8];
                #pragma unroll
                for (int j = 0; j < 25; j++) acc += srow[25 + j] * sm->ve[kp][j][e8];
                #pragma unroll
                for (int j = 0; j < 25; j++) acc += srow[50 + j] * sm->ve[kn][j][e8];
                acc *= 0.1f;
            }
            g_ret1[b*38400 + g*4800 + h2*1200 + k*400 + i*16 + e] = acc;
        }
        __syncthreads();
    }
}

// -------------------- kernel 5: 128-channel L2 norms + bs group-norm --------------------
__global__ void k_norm2()
{
    int b = blockIdx.x, p = threadIdx.x;
    if (p < 300) {
        const float* base = &g_ret1[b*38400 + p];
        float ss = 0.f;
        #pragma unroll 8
        for (int c = 0; c < 128; c++) { float v = base[c*300]; ss += v*v; }
        g_rdnm[b*300 + p] = 1.0f / fmaxf(sqrtf(ss), EPS_N);
    }
    if (p < 224) {
        int h2 = p / 56, t = p % 56;
        float sv = 0.f, sq = 0.f;
        #pragma unroll
        for (int g = 0; g < 8; g++) {
            float v = g_bsg[((b*8 + g)*4 + h2)*75 + t];
            sv += v; sq += v*v;
        }
        g_bsn[b*224 + p] = sv / fmaxf(sqrtf(sq), EPS_N);
    }
}

// -------------------- kernel 6: normalize + pair-sum -> sorted output --------------------
__global__ void k_outs()
{
    int idx = blockIdx.x*blockDim.x + threadIdx.x;
    if (idx >= BATCH*4*56*64) return;
    int e  = idx & 63;
    int t2 = (idx >> 6) % 56;
    int h4 = (idx / (64*56)) & 3;
    int b  = idx / (64*56*4);
    int k4 = t2 / 25, i4 = t2 % 25;
    int f0 = h4*9600 + k4*3200 + i4*128 + 2*e;
    const float* rb = &g_ret1[b*38400];
    const float* rd = &g_rdnm[b*300];
    g_outs[idx] = rb[f0] * rd[f0 % 300] + rb[f0 + 1] * rd[(f0 + 1) % 300];
}

// -------------------- kernel 7: undo-gather, hash softmax, transposed store --------------------
__global__ void k_final(float* __restrict__ out)
{
    int b = blockIdx.x; int n = b / WAX, w = b % WAX;
    __shared__ int   u[224];
    __shared__ float prob[4][56];
    for (int p = threadIdx.x; p < 224; p += blockDim.x) u[p] = g_undo[b*224 + p];
    __syncthreads();
    if (threadIdx.x < 56) {
        int t = threadIdx.x;
        float bv[4]; float m = -1e30f;
        #pragma unroll
        for (int h = 0; h < 4; h++) { bv[h] = g_bsn[b*224 + u[h*56 + t]]; m = fmaxf(m, bv[h]); }
        float sum = 0.f;
        #pragma unroll
        for (int h = 0; h < 4; h++) { float e = expf(bv[h] - m); prob[h][t] = e; sum += e; }
        float rs = 1.0f / sum;
        #pragma unroll
        for (int h = 0; h < 4; h++) prob[h][t] *= rs;
    }
    __syncthreads();
    for (int o = threadIdx.x; o < 56*64; o += blockDim.x) {
        int t = o >> 6, e = o & 63;
        float acc = 0.f;
        #pragma unroll
        for (int h = 0; h < 4; h++)
            acc += g_outs[(b*224 + u[h*56 + t])*64 + e] * prob[h][t];
        out[((n*OUTC + e)*HAX + t)*WAX + w] = acc;
    }
}

// -------------------- launch --------------------
extern "C" void kernel_launch(void* const* d_in, const int* in_sizes, int n_in,
                              void* d_out, int out_size)
{
    const float* x     = (const float*)d_in[0];
    const float* cw    = (const float*)d_in[1];
    const float* gamma = (const float*)d_in[2];
    const float* beta  = (const float*)d_in[3];
    const float* rel   = (const float*)d_in[4];
    const float* rot   = (const float*)d_in[5];
    float* out = (float*)d_out;

    cudaFuncSetAttribute(k_attn, cudaFuncAttributeMaxDynamicSharedMemorySize,
                         (int)sizeof(SmemAtt));

    k_convbn<<<BATCH, 256>>>(x, cw, gamma, beta);
    k_codes <<<(BATCH*224 + 255)/256, 256>>>(rot);
    k_sort  <<<1, 128>>>();
    k_attn  <<<dim3(BATCH, 4), 256, sizeof(SmemAtt)>>>(rel);
    k_norm2 <<<BATCH, 320>>>();
    k_outs  <<<(BATCH*4*56*64 + 255)/256, 256>>>();
    k_final <<<BATCH, 256>>>(out);
}

// round 2
// speedup vs baseline: 2.0279x; 2.0279x over previous
#include <cuda_runtime.h>
#include <math.h>

// Problem constants (fixed shapes)
#define NB      2
#define CIN     64
#define HAX     56
#define WAX     56
#define BATCH   112          // NB*WAX
#define OUTC    64
#define CHUNK   25
#define KBLK    3
#define PADLEN  19
#define EPS_N   5e-5f

// -------------------- scratch (device globals; no allocation) --------------------
__device__ float g_wmatch[BATCH*56*32];       // (b, t, 32)
__device__ float g_vmatch[BATCH*56*64];       // (b, t, 64)
__device__ int   g_indices[BATCH*224];
__device__ int   g_undo   [BATCH*224];
__device__ float g_ret1[BATCH*38400];         // (b, g,h2,k,i,e16) flat
__device__ float g_bsg [BATCH*8*4*75];        // (b, g, h2, t75)

// -------------------- kernel 1: conv1x1+BN + hash codes + stable rank sort --------------------
__global__ __launch_bounds__(256)
void k_prep(const float* __restrict__ x, const float* __restrict__ cw,
            const float* __restrict__ gamma, const float* __restrict__ beta,
            const float* __restrict__ rot)
{
    __shared__ float xs[CIN*HAX];    // (c,h)
    __shared__ float ws[96*CIN];     // (o,c)
    __shared__ float wm[HAX*32];     // w_match rows for codes
    __shared__ int   cd[224];
    int b = blockIdx.x, n = b / WAX, w = b % WAX;

    for (int i = threadIdx.x; i < CIN*HAX; i += 256) {
        int c = i / HAX, h = i % HAX;
        xs[i] = x[((n*CIN + c)*HAX + h)*WAX + w];
    }
    for (int i = threadIdx.x; i < 96*CIN; i += 256) ws[i] = cw[i];
    __syncthreads();

    const float inv = rsqrtf(1.0f + 1e-5f);
    for (int i = threadIdx.x; i < 96*HAX; i += 256) {
        int o = i / HAX, h = i % HAX;
        float acc = 0.f;
        #pragma unroll 16
        for (int c = 0; c < CIN; c++) acc += ws[o*CIN + c] * xs[c*HAX + h];
        float v = acc * inv * gamma[o] + beta[o];
        // raw reshape (96,56) -> (56,96)
        int t = i / 96, f = i % 96;
        if (f < 32) { wm[t*32 + f] = v; g_wmatch[(b*56 + t)*32 + f] = v; }
        else        g_vmatch[(b*56 + t)*64 + (f - 32)] = v;
    }
    __syncthreads();

    if (threadIdx.x < 224) {
        int r = threadIdx.x, hh = r / 56, t = r % 56;
        float acc = 0.f;
        #pragma unroll
        for (int f = 0; f < 32; f++) acc += wm[t*32 + f] * rot[f*4 + hh];
        cd[r] = ((acc < 0.0f) ? 1 : 0) + 2*hh;
    }
    __syncthreads();

    if (threadIdx.x < 224) {
        int p = threadIdx.x, c = cd[p], rank = 0;
        for (int q = 0; q < 224; q++) {
            int cq = cd[q];
            rank += (cq < c) || (cq == c && q < p);
        }
        g_indices[b*224 + rank] = p;
        g_undo   [b*224 + p]    = rank;
    }
}

// -------------------- kernel 2: fused chunked attention --------------------
struct SmemAtt {
    float w_t[8][3][25][4];   // raw query rows
    float w_n[8][3][25][4];   // L2-normalized key rows
    float v_t[8][3][25][8];
    float we [3][25][4];
    float ve [3][25][8];
    float s  [8][25][75];     // scores (in place), per-k
};

__global__ __launch_bounds__(512, 2)
void k_attn(const float* __restrict__ relative)
{
    extern __shared__ char smraw[];
    SmemAtt* sm = reinterpret_cast<SmemAtt*>(smraw);
    const int b = blockIdx.x, h2 = blockIdx.y;
    const int tid = threadIdx.x;

    // ---- gather tiles ----
    for (int idx = tid; idx < 8*75; idx += 512) {
        int g = idx / 75, rem = idx % 75;
        int k = rem / 25, i = rem % 25;
        int tc  = (g & 1)*300 + h2*75 + rem;
        int hp  = g >> 1;
        int tp  = tc >> 3, c = tc & 7;
        int t56 = (tp < 56) ? tp : tp - PADLEN;
        int src = g_indices[b*224 + hp*56 + t56] % 56;
        float4 wv = *reinterpret_cast<const float4*>(&g_wmatch[(b*56 + src)*32 + 4*c]);
        *reinterpret_cast<float4*>(sm->w_t[g][k][i]) = wv;
        float nn = wv.x*wv.x + wv.y*wv.y + wv.z*wv.z + wv.w*wv.w;
        float in = 1.0f / fmaxf(sqrtf(nn), EPS_N);
        float4 wn; wn.x = wv.x*in; wn.y = wv.y*in; wn.z = wv.z*in; wn.w = wv.w*in;
        *reinterpret_cast<float4*>(sm->w_n[g][k][i]) = wn;
        const float4* vp = reinterpret_cast<const float4*>(&g_vmatch[(b*56 + src)*64 + 8*c]);
        *reinterpret_cast<float4*>(&sm->v_t[g][k][i][0]) = vp[0];
        *reinterpret_cast<float4*>(&sm->v_t[g][k][i][4]) = vp[1];
    }
    for (int idx = tid; idx < 75; idx += 512) {
        int k = idx / 25, i = idx % 25;
        int t56 = (idx < 56) ? idx : idx - PADLEN;
        const float* rr = &relative[t56*12];
        #pragma unroll
        for (int e = 0; e < 4; e++) sm->we[k][i][e] = rr[e];
        #pragma unroll
        for (int e = 0; e < 8; e++) sm->ve[k][i][e] = rr[4 + e];
    }
    __syncthreads();

    for (int k = 0; k < KBLK; k++) {
        const int kp = (k + 2) % 3, kn = (k + 1) % 3;

        // ---- phase 1: scores + cross-group L2 norm (queries cached in regs) ----
        if (tid < 500) {
            int row = tid / 20, col = tid % 20;   // row: 0..24, col: 0..19
            float4 a[8];
            #pragma unroll
            for (int g = 0; g < 8; g++) a[g] = *reinterpret_cast<const float4*>(sm->w_t[g][k][row]);
            #pragma unroll
            for (int jj4 = 0; jj4 < 4; jj4++) {
                int j = col*4 + jj4;
                if (j < 75) {
                    int kk, jj;
                    if (j < 25)      { kk = k;  jj = j;      }
                    else if (j < 50) { kk = kp; jj = j - 25; }
                    else             { kk = kn; jj = j - 50; }
                    float4 we4 = *reinterpret_cast<const float4*>(sm->we[kk][jj]);
                    float vals[8]; float ssq = 0.f;
                    #pragma unroll
                    for (int g = 0; g < 8; g++) {
                        float4 mn = *reinterpret_cast<const float4*>(sm->w_n[g][kk][jj]);
                        float raw = a[g].x*mn.x + a[g].y*mn.y + a[g].z*mn.z + a[g].w*mn.w;
                        float emb = 0.1f*(a[g].x*we4.x + a[g].y*we4.y + a[g].z*we4.z + a[g].w*we4.w);
                        vals[g] = raw + emb;
                        ssq += raw*raw + emb*emb;
                    }
                    float rdv = 1.0f / fmaxf(sqrtf(ssq), EPS_N);
                    #pragma unroll
                    for (int g = 0; g < 8; g++) sm->s[g][row][j] = vals[g]*rdv;
                }
            }
        }
        __syncthreads();

        // ---- phase 2: logsumexp per (g,i) row; normalized score in place ----
        {
            int warp = tid >> 5, lane = tid & 31;
            for (int rowi = warp; rowi < 200; rowi += 16) {
                int g = rowi / 25, i = rowi % 25;
                float* r = sm->s[g][i];
                float m = -1e30f;
                for (int j = lane; j < 75; j += 32) m = fmaxf(m, r[j]);
                #pragma unroll
                for (int o = 16; o; o >>= 1) m = fmaxf(m, __shfl_xor_sync(~0u, m, o));
                float sum = 0.f;
                for (int j = lane; j < 75; j += 32) { float e = __expf(r[j] - m); r[j] = e; sum += e; }
                #pragma unroll
                for (int o = 16; o; o >>= 1) sum += __shfl_xor_sync(~0u, sum, o);
                float rs = 1.0f / sum;
                for (int j = lane; j < 75; j += 32) r[j] *= rs;
                if (lane == 0)
                    g_bsg[((b*8 + g)*4 + h2)*75 + k*25 + i] = m + __logf(sum);
            }
        }
        __syncthreads();

        // ---- phase 3: score @ V (float4 over channels) ----
        for (int it = tid; it < 8*25*4; it += 512) {
            int g = it / 100, rem = it % 100, i = rem / 4, q = rem % 4;
            const float* srow = sm->s[g][i];
            float4 acc = make_float4(0.f, 0.f, 0.f, 0.f);
            if (q < 2) {
                const float4* v0 = reinterpret_cast<const float4*>(&sm->v_t[g][k ][0][4*q]);
                const float4* v1 = reinterpret_cast<const float4*>(&sm->v_t[g][kp][0][4*q]);
                const float4* v2 = reinterpret_cast<const float4*>(&sm->v_t[g][kn][0][4*q]);
                #pragma unroll
                for (int j = 0; j < 25; j++) {
                    float s0 = srow[j], s1 = srow[25+j], s2 = srow[50+j];
                    float4 a0 = v0[2*j], a1 = v1[2*j], a2 = v2[2*j];
                    acc.x += s0*a0.x + s1*a1.x + s2*a2.x;
                    acc.y += s0*a0.y + s1*a1.y + s2*a2.y;
                    acc.z += s0*a0.z + s1*a1.z + s2*a2.z;
                    acc.w += s0*a0.w + s1*a1.w + s2*a2.w;
                }
            } else {
                int q2 = q - 2;
                const float4* e0 = reinterpret_cast<const float4*>(&sm->ve[k ][0][4*q2]);
                const float4* e1 = reinterpret_cast<const float4*>(&sm->ve[kp][0][4*q2]);
                const float4* e2 = reinterpret_cast<const float4*>(&sm->ve[kn][0][4*q2]);
                #pragma unroll
                for (int j = 0; j < 25; j++) {
                    float s0 = srow[j], s1 = srow[25+j], s2 = srow[50+j];
                    float4 a0 = e0[2*j], a1 = e1[2*j], a2 = e2[2*j];
                    acc.x += s0*a0.x + s1*a1.x + s2*a2.x;
                    acc.y += s0*a0.y + s1*a1.y + s2*a2.y;
                    acc.z += s0*a0.z + s1*a1.z + s2*a2.z;
                    acc.w += s0*a0.w + s1*a1.w + s2*a2.w;
                }
                acc.x *= 0.1f; acc.y *= 0.1f; acc.z *= 0.1f; acc.w *= 0.1f;
            }
            *reinterpret_cast<float4*>(&g_ret1[b*38400 + g*4800 + h2*1200 + k*400 + i*16 + 4*q]) = acc;
        }
        __syncthreads();
    }
}

// -------------------- kernel 3: norms + undo-gather + hash softmax + store --------------------
__global__ __launch_bounds__(256)
void k_fin(float* __restrict__ out)
{
    __shared__ float rd[300];
    __shared__ float bsn[224];
    __shared__ int   u[224];
    __shared__ float prob[4][56];
    int b = blockIdx.x, n = b / WAX, w = b % WAX;
    const float* rb = &g_ret1[b*38400];

    for (int p = threadIdx.x; p < 300; p += 256) {
        float ss = 0.f;
        #pragma unroll 8
        for (int c = 0; c < 128; c++) { float v = rb[c*300 + p]; ss += v*v; }
        rd[p] = 1.0f / fmaxf(sqrtf(ss), EPS_N);
    }
    for (int p = threadIdx.x; p < 224; p += 256) {
        int h2 = p / 56, t = p % 56;
        float sv = 0.f, sq = 0.f;
        #pragma unroll
        for (int g = 0; g < 8; g++) {
            float v = g_bsg[((b*8 + g)*4 + h2)*75 + t];
            sv += v; sq += v*v;
        }
        bsn[p] = sv / fmaxf(sqrtf(sq), EPS_N);
        u[p] = g_undo[b*224 + p];
    }
    __syncthreads();

    if (threadIdx.x < 56) {
        int t = threadIdx.x;
        float bv[4]; float m = -1e30f;
        #pragma unroll
        for (int h = 0; h < 4; h++) { bv[h] = bsn[u[h*56 + t]]; m = fmaxf(m, bv[h]); }
        float sum = 0.f;
        #pragma unroll
        for (int h = 0; h < 4; h++) { float e = __expf(bv[h] - m); prob[h][t] = e; sum += e; }
        float rs = 1.0f / sum;
        #pragma unroll
        for (int h = 0; h < 4; h++) prob[h][t] *= rs;
    }
    __syncthreads();

    for (int o = threadIdx.x; o < 56*32; o += 256) {
        int t = o >> 5, e2 = o & 31;       // e2 covers channels (2*e2, 2*e2+1)
        float acc0 = 0.f, acc1 = 0.f;
        #pragma unroll
        for (int h = 0; h < 4; h++) {
            int p  = u[h*56 + t];
            int h4 = p / 56, t2 = p % 56, k4 = t2 / 25, i4 = t2 % 25;
            int f0 = h4*9600 + k4*3200 + i4*128 + 4*e2;
            float4 rv = *reinterpret_cast<const float4*>(&rb[f0]);
            int m0 = (200*k4 + 128*i4 + 4*e2) % 300;
            int m2 = m0 + 2; if (m2 >= 300) m2 -= 300;
            float ph = prob[h][t];
            acc0 += (rv.x*rd[m0] + rv.y*rd[m0+1]) * ph;
            acc1 += (rv.z*rd[m2] + rv.w*rd[m2+1]) * ph;
        }
        int e = 2*e2;
        out[((n*OUTC + e    )*HAX + t)*WAX + w] = acc0;
        out[((n*OUTC + e + 1)*HAX + t)*WAX + w] = acc1;
    }
}

// -------------------- launch --------------------
extern "C" void kernel_launch(void* const* d_in, const int* in_sizes, int n_in,
                              void* d_out, int out_size)
{
    const float* x     = (const float*)d_in[0];
    const float* cw    = (const float*)d_in[1];
    const float* gamma = (const float*)d_in[2];
    const float* beta  = (const float*)d_in[3];
    const float* rel   = (const float*)d_in[4];
    const float* rot   = (const float*)d_in[5];
    float* out = (float*)d_out;

    cudaFuncSetAttribute(k_attn, cudaFuncAttributeMaxDynamicSharedMemorySize,
                         (int)sizeof(SmemAtt));

    k_prep<<<BATCH, 256>>>(x, cw, gamma, beta, rot);
    k_attn<<<dim3(BATCH, 4), 512, sizeof(SmemAtt)>>>(rel);
    k_fin <<<BATCH, 256>>>(out);
}

// round 3
// speedup vs baseline: 2.4673x; 1.2167x over previous
#include <cuda_runtime.h>
#include <math.h>

#define NB      2
#define CIN     64
#define HAX     56
#define WAX     56
#define BATCH   112
#define OUTC    64
#define CHUNK   25
#define PADLEN  19
#define EPS_N   5e-5f

// -------------------- scratch --------------------
__device__ float g_wmatch[BATCH*56*32];
__device__ float g_vmatch[BATCH*56*64];
__device__ int   g_indices[BATCH*224];
__device__ int   g_undo   [BATCH*224];
__device__ float g_ret1[BATCH*38400];         // (b, g,h2,k,i,e16)
__device__ float g_bsg [BATCH*8*4*75];        // (b, g, h2, t75)

// -------------------- kernel 1: conv1x1+BN + hash codes + stable rank sort --------------------
__global__ __launch_bounds__(512)
void k_prep(const float* __restrict__ x, const float* __restrict__ cw,
            const float* __restrict__ gamma, const float* __restrict__ beta,
            const float* __restrict__ rot)
{
    __shared__ float xs[CIN*HAX];     // (c,h)
    __shared__ float wst[CIN*96];     // (c,o) transposed weights
    __shared__ float gb[192];
    __shared__ float wm[HAX*32];
    __shared__ int   cd[224];
    int b = blockIdx.x, n = b / WAX, w = b % WAX;
    int tid = threadIdx.x;

    for (int i = tid; i < CIN*HAX; i += 512) {
        int c = i / HAX, h = i % HAX;
        xs[i] = x[((n*CIN + c)*HAX + h)*WAX + w];
    }
    for (int i = tid; i < 96*CIN; i += 512) {
        int o = i / CIN, c = i % CIN;
        wst[c*96 + o] = cw[i];
    }
    if (tid < 96) { gb[tid] = gamma[tid]; gb[96 + tid] = beta[tid]; }
    __syncthreads();

    const float inv = rsqrtf(1.0f + 1e-5f);
    for (int u = tid; u < 24*HAX; u += 512) {
        int o4 = u / HAX, h = u % HAX;
        float4 acc = make_float4(0.f, 0.f, 0.f, 0.f);
        #pragma unroll 8
        for (int c = 0; c < CIN; c++) {
            float xv = xs[c*HAX + h];
            float4 w4 = *reinterpret_cast<const float4*>(&wst[c*96 + 4*o4]);
            acc.x += xv*w4.x; acc.y += xv*w4.y; acc.z += xv*w4.z; acc.w += xv*w4.w;
        }
        float av[4] = {acc.x, acc.y, acc.z, acc.w};
        #pragma unroll
        for (int oo = 0; oo < 4; oo++) {
            int o = 4*o4 + oo;
            float v = av[oo]*inv*gb[o] + gb[96 + o];
            int flat = o*HAX + h, t = flat / 96, f = flat % 96;
            if (f < 32) { wm[t*32 + f] = v; g_wmatch[(b*56 + t)*32 + f] = v; }
            else        g_vmatch[(b*56 + t)*64 + (f - 32)] = v;
        }
    }
    __syncthreads();

    if (tid < 224) {
        int hh = tid / 56, t = tid % 56;
        float acc = 0.f;
        #pragma unroll
        for (int f = 0; f < 32; f++) acc += wm[t*32 + f] * rot[f*4 + hh];
        cd[tid] = ((acc < 0.0f) ? 1 : 0) + 2*hh;
    }
    __syncthreads();

    if (tid < 224) {
        int p = tid, c = cd[p], rank = 0;
        for (int q = 0; q < 224; q++) {
            int cq = cd[q];
            rank += (cq < c) || (cq == c && q < p);
        }
        g_indices[b*224 + rank] = p;
        g_undo   [b*224 + p]    = rank;
    }
}

// -------------------- kernel 2: fused chunked attention (split-k grid) --------------------
struct SmemAtt {
    float w_t[8][3][25][4];   // raw query rows (all k, for simplicity)
    float w_n[8][3][25][4];   // L2-normalized key rows
    float v_t[8][3][25][8];
    float we [3][25][4];
    float ve [3][25][8];
    float s  [8][25][75];
};

__global__ __launch_bounds__(512, 2)
void k_attn(const float* __restrict__ relative)
{
    extern __shared__ char smraw[];
    SmemAtt* sm = reinterpret_cast<SmemAtt*>(smraw);
    const int b = blockIdx.x, h2 = blockIdx.y, k = blockIdx.z;
    const int kp = (k + 2) % 3, kn = (k + 1) % 3;
    const int tid = threadIdx.x;

    // ---- gather tiles ----
    for (int idx = tid; idx < 8*75; idx += 512) {
        int g = idx / 75, rem = idx % 75;
        int kk = rem / 25, i = rem % 25;
        int tc  = (g & 1)*300 + h2*75 + rem;
        int hp  = g >> 1;
        int tp  = tc >> 3, c = tc & 7;
        int t56 = (tp < 56) ? tp : tp - PADLEN;
        int src = g_indices[b*224 + hp*56 + t56] % 56;
        float4 wv = *reinterpret_cast<const float4*>(&g_wmatch[(b*56 + src)*32 + 4*c]);
        *reinterpret_cast<float4*>(sm->w_t[g][kk][i]) = wv;
        float nn = wv.x*wv.x + wv.y*wv.y + wv.z*wv.z + wv.w*wv.w;
        float in = 1.0f / fmaxf(sqrtf(nn), EPS_N);
        float4 wn; wn.x = wv.x*in; wn.y = wv.y*in; wn.z = wv.z*in; wn.w = wv.w*in;
        *reinterpret_cast<float4*>(sm->w_n[g][kk][i]) = wn;
        const float4* vp = reinterpret_cast<const float4*>(&g_vmatch[(b*56 + src)*64 + 8*c]);
        *reinterpret_cast<float4*>(&sm->v_t[g][kk][i][0]) = vp[0];
        *reinterpret_cast<float4*>(&sm->v_t[g][kk][i][4]) = vp[1];
    }
    for (int idx = tid; idx < 75; idx += 512) {
        int kk = idx / 25, i = idx % 25;
        int t56 = (idx < 56) ? idx : idx - PADLEN;
        const float* rr = &relative[t56*12];
        #pragma unroll
        for (int e = 0; e < 4; e++) sm->we[kk][i][e] = rr[e];
        #pragma unroll
        for (int e = 0; e < 8; e++) sm->ve[kk][i][e] = rr[4 + e];
    }
    __syncthreads();

    // ---- phase 1: scores + cross-group L2 norm ----
    if (tid < 500) {
        int row = tid / 20, col = tid % 20;
        float4 a[8];
        #pragma unroll
        for (int g = 0; g < 8; g++) a[g] = *reinterpret_cast<const float4*>(sm->w_t[g][k][row]);
        #pragma unroll
        for (int jj4 = 0; jj4 < 4; jj4++) {
            int j = col*4 + jj4;
            if (j < 75) {
                int kk, jj;
                if (j < 25)      { kk = k;  jj = j;      }
                else if (j < 50) { kk = kp; jj = j - 25; }
                else             { kk = kn; jj = j - 50; }
                float4 we4 = *reinterpret_cast<const float4*>(sm->we[kk][jj]);
                float vals[8]; float ssq = 0.f;
                #pragma unroll
                for (int g = 0; g < 8; g++) {
                    float4 mn = *reinterpret_cast<const float4*>(sm->w_n[g][kk][jj]);
                    float raw = a[g].x*mn.x + a[g].y*mn.y + a[g].z*mn.z + a[g].w*mn.w;
                    float emb = 0.1f*(a[g].x*we4.x + a[g].y*we4.y + a[g].z*we4.z + a[g].w*we4.w);
                    vals[g] = raw + emb;
                    ssq += raw*raw + emb*emb;
                }
                float rdv = 1.0f / fmaxf(sqrtf(ssq), EPS_N);
                #pragma unroll
                for (int g = 0; g < 8; g++) sm->s[g][row][j] = vals[g]*rdv;
            }
        }
    }
    __syncthreads();

    // ---- phase 2: logsumexp per (g,i) row ----
    {
        int warp = tid >> 5, lane = tid & 31;
        for (int rowi = warp; rowi < 200; rowi += 16) {
            int g = rowi / 25, i = rowi % 25;
            float* r = sm->s[g][i];
            float m = -1e30f;
            for (int j = lane; j < 75; j += 32) m = fmaxf(m, r[j]);
            #pragma unroll
            for (int o = 16; o; o >>= 1) m = fmaxf(m, __shfl_xor_sync(~0u, m, o));
            float sum = 0.f;
            for (int j = lane; j < 75; j += 32) { float e = __expf(r[j] - m); r[j] = e; sum += e; }
            #pragma unroll
            for (int o = 16; o; o >>= 1) sum += __shfl_xor_sync(~0u, sum, o);
            float rs = 1.0f / sum;
            for (int j = lane; j < 75; j += 32) r[j] *= rs;
            if (lane == 0)
                g_bsg[((b*8 + g)*4 + h2)*75 + k*25 + i] = m + __logf(sum);
        }
    }
    __syncthreads();

    // ---- phase 3: score @ V, i-pair register tiling ----
    // unit = (g, i-pair, q): 8 * 13 * 4 = 416 units
    if (tid < 416) {
        int g  = tid / 52, rem = tid % 52;
        int ip = rem / 4,  q   = rem % 4;
        int i0 = 2*ip;
        bool has1 = (i0 + 1) < 25;
        const float* s0 = sm->s[g][i0];
        const float* s1 = sm->s[g][i0 + (has1 ? 1 : 0)];
        float4 acc0 = make_float4(0.f,0.f,0.f,0.f);
        float4 acc1 = make_float4(0.f,0.f,0.f,0.f);
        int korder[3] = {k, kp, kn};
        #pragma unroll
        for (int seg = 0; seg < 3; seg++) {
            int kk = korder[seg];
            const float4* vp = (q < 2)
                ? reinterpret_cast<const float4*>(&sm->v_t[g][kk][0][4*q])
                : reinterpret_cast<const float4*>(&sm->ve[kk][0][4*(q-2)]);
            int base = seg*25;
            #pragma unroll
            for (int j = 0; j < 25; j++) {
                float4 v = vp[2*j];
                float a = s0[base + j];
                acc0.x += a*v.x; acc0.y += a*v.y; acc0.z += a*v.z; acc0.w += a*v.w;
                float c = s1[base + j];
                acc1.x += c*v.x; acc1.y += c*v.y; acc1.z += c*v.z; acc1.w += c*v.w;
            }
        }
        if (q >= 2) {
            acc0.x *= 0.1f; acc0.y *= 0.1f; acc0.z *= 0.1f; acc0.w *= 0.1f;
            acc1.x *= 0.1f; acc1.y *= 0.1f; acc1.z *= 0.1f; acc1.w *= 0.1f;
        }
        int base_out = b*38400 + g*4800 + h2*1200 + k*400 + 4*q;
        *reinterpret_cast<float4*>(&g_ret1[base_out + i0*16]) = acc0;
        if (has1)
            *reinterpret_cast<float4*>(&g_ret1[base_out + (i0+1)*16]) = acc1;
    }
}

// -------------------- kernel 3: norms + undo-gather + hash softmax + store --------------------
__global__ __launch_bounds__(512)
void k_fin(float* __restrict__ out)
{
    __shared__ float rd[300];
    __shared__ float bsn[224];
    __shared__ int   u[224];
    __shared__ float prob[4][56];
    int b = blockIdx.x, n = b / WAX, w = b % WAX;
    int tid = threadIdx.x;
    const float* rb = &g_ret1[b*38400];

    if (tid < 300) {
        float ss = 0.f;
        #pragma unroll 16
        for (int c = 0; c < 128; c++) { float v = rb[c*300 + tid]; ss += v*v; }
        rd[tid] = 1.0f / fmaxf(sqrtf(ss), EPS_N);
    }
    if (tid < 224) {
        int h2 = tid / 56, t = tid % 56;
        float sv = 0.f, sq = 0.f;
        #pragma unroll
        for (int g = 0; g < 8; g++) {
            float v = g_bsg[((b*8 + g)*4 + h2)*75 + t];
            sv += v; sq += v*v;
        }
        bsn[tid] = sv / fmaxf(sqrtf(sq), EPS_N);
        u[tid] = g_undo[b*224 + tid];
    }
    __syncthreads();

    if (tid < 56) {
        int t = tid;
        float bv[4]; float m = -1e30f;
        #pragma unroll
        for (int h = 0; h < 4; h++) { bv[h] = bsn[u[h*56 + t]]; m = fmaxf(m, bv[h]); }
        float sum = 0.f;
        #pragma unroll
        for (int h = 0; h < 4; h++) { float e = __expf(bv[h] - m); prob[h][t] = e; sum += e; }
        float rs = 1.0f / sum;
        #pragma unroll
        for (int h = 0; h < 4; h++) prob[h][t] *= rs;
    }
    __syncthreads();

    for (int o = tid; o < 56*32; o += 512) {
        int t = o >> 5, e2 = o & 31;
        float acc0 = 0.f, acc1 = 0.f;
        #pragma unroll
        for (int h = 0; h < 4; h++) {
            int p  = u[h*56 + t];
            int h4 = p / 56, t2 = p % 56, k4 = t2 / 25, i4 = t2 % 25;
            int f0 = h4*9600 + k4*3200 + i4*128 + 4*e2;
            float4 rv = *reinterpret_cast<const float4*>(&rb[f0]);
            int m0 = (200*k4 + 128*i4 + 4*e2) % 300;
            int m2 = m0 + 2; if (m2 >= 300) m2 -= 300;
            float ph = prob[h][t];
            acc0 += (rv.x*rd[m0] + rv.y*rd[m0+1]) * ph;
            acc1 += (rv.z*rd[m2] + rv.w*rd[m2+1]) * ph;
        }
        int e = 2*e2;
        out[((n*OUTC + e    )*HAX + t)*WAX + w] = acc0;
        out[((n*OUTC + e + 1)*HAX + t)*WAX + w] = acc1;
    }
}

// -------------------- launch --------------------
extern "C" void kernel_launch(void* const* d_in, const int* in_sizes, int n_in,
                              void* d_out, int out_size)
{
    const float* x     = (const float*)d_in[0];
    const float* cw    = (const float*)d_in[1];
    const float* gamma = (const float*)d_in[2];
    const float* beta  = (const float*)d_in[3];
    const float* rel   = (const float*)d_in[4];
    const float* rot   = (const float*)d_in[5];
    float* out = (float*)d_out;

    cudaFuncSetAttribute(k_attn, cudaFuncAttributeMaxDynamicSharedMemorySize,
                         (int)sizeof(SmemAtt));

    k_prep<<<BATCH, 512>>>(x, cw, gamma, beta, rot);
    k_attn<<<dim3(BATCH, 4, 3), 512, sizeof(SmemAtt)>>>(rel);
    k_fin <<<BATCH, 512>>>(out);
}